// round 2
// baseline (speedup 1.0000x reference)
#include <cuda_runtime.h>
#include <math.h>

#define NN 50000
#define NE 800000
#define ETOT (NE + NN)          // edges + self loops
#define HEADS 8
#define HID 32
#define D1 (HEADS * HID)        // 256
#define D2 16
#define NEG_SLOPE 0.2f

// ---------------- scratch (device globals; no allocations allowed) ----------
__device__ int g_degree[NN];
__device__ int g_offsets[NN + 1];
__device__ int g_cursor[NN];
__device__ int g_csr_src[ETOT];

__device__ __align__(16) float g_h1[NN * D1];     // layer1 transformed features
__device__ float g_as1[NN * HEADS];
__device__ float g_ad1[NN * HEADS];
__device__ __align__(16) float g_hmid[NN * D1];   // elu(layer1 out) = layer2 input
__device__ __align__(16) float g_h2[NN * D2];     // layer2 transformed features
__device__ float g_as2[NN];
__device__ float g_ad2[NN];

__device__ __forceinline__ float lrelu(float x) {
    return x > 0.f ? x : NEG_SLOPE * x;
}

// ---------------- CSR build --------------------------------------------------
__global__ void k_zero_deg() {
    int i = blockIdx.x * blockDim.x + threadIdx.x;
    if (i < NN) g_degree[i] = 0;
}

__global__ void k_hist(const int* __restrict__ ei) {
    int e = blockIdx.x * blockDim.x + threadIdx.x;
    if (e >= ETOT) return;
    int dst = (e < NE) ? ei[NE + e] : (e - NE);
    atomicAdd(&g_degree[dst], 1);
}

__global__ void k_scan() {
    __shared__ int sh[1024];
    int t = threadIdx.x;
    const int CH = (NN + 1023) >> 10;   // 49
    int b = t * CH;
    int e = min(b + CH, NN);
    int s = 0;
    for (int i = b; i < e; i++) s += g_degree[i];
    sh[t] = s;
    __syncthreads();
    for (int off = 1; off < 1024; off <<= 1) {
        int v = 0;
        if (t >= off) v = sh[t - off];
        __syncthreads();
        sh[t] += v;
        __syncthreads();
    }
    int run = (t == 0) ? 0 : sh[t - 1];
    for (int i = b; i < e; i++) {
        g_offsets[i] = run;
        g_cursor[i]  = run;
        run += g_degree[i];
    }
    if (t == 1023) g_offsets[NN] = sh[1023];
}

__global__ void k_scatter(const int* __restrict__ ei) {
    int e = blockIdx.x * blockDim.x + threadIdx.x;
    if (e >= ETOT) return;
    int src, dst;
    if (e < NE) { src = ei[e]; dst = ei[NE + e]; }
    else        { src = e - NE; dst = e - NE; }
    int slot = atomicAdd(&g_cursor[dst], 1);
    g_csr_src[slot] = src;
}

// ---------------- layer 1: node transform -----------------------------------
// h1 = x @ W1 (3x256);  a_s/a_d via per-head (per-warp segment) reductions
__global__ void k_l1_node(const float* __restrict__ x,
                          const float* __restrict__ W1,
                          const float* __restrict__ att_s,
                          const float* __restrict__ att_d) {
    int k = threadIdx.x;                 // 0..255 output channel
    int lane = k & 31;
    int head = k >> 5;
    float w0 = W1[k], w1 = W1[256 + k], w2 = W1[512 + k];
    float av = att_s[k], dv = att_d[k];
    for (int n = blockIdx.x; n < NN; n += gridDim.x) {
        float x0 = __ldg(&x[n * 3 + 0]);
        float x1 = __ldg(&x[n * 3 + 1]);
        float x2 = __ldg(&x[n * 3 + 2]);
        float h = fmaf(x0, w0, fmaf(x1, w1, x2 * w2));
        g_h1[n * D1 + k] = h;
        float sa = h * av, sd = h * dv;
        #pragma unroll
        for (int off = 16; off > 0; off >>= 1) {
            sa += __shfl_xor_sync(0xffffffffu, sa, off);
            sd += __shfl_xor_sync(0xffffffffu, sd, off);
        }
        if (lane == 0) {
            g_as1[n * HEADS + head] = sa;
            g_ad1[n * HEADS + head] = sd;
        }
    }
}

// ---------------- layer 1: softmax + aggregate + bias + ELU -----------------
// one warp per dst node
__global__ void k_l1_agg(const float* __restrict__ bias1) {
    int n = blockIdx.x * 8 + (threadIdx.x >> 5);
    if (n >= NN) return;
    int lane = threadIdx.x & 31;
    int base = g_offsets[n];
    int deg  = g_offsets[n + 1] - base;

    // phase A/B layout: lane = g*8 + h  (4 edge groups x 8 heads)
    int h = lane & 7;
    int g = lane >> 3;
    float adh = g_ad1[n * HEADS + h];

    float m = __int_as_float(0xff800000);   // -inf
    for (int j = g; j < deg; j += 4) {
        int s = g_csr_src[base + j];
        float e = lrelu(g_as1[s * HEADS + h] + adh);
        m = fmaxf(m, e);
    }
    m = fmaxf(m, __shfl_xor_sync(0xffffffffu, m, 8));
    m = fmaxf(m, __shfl_xor_sync(0xffffffffu, m, 16));

    float sum = 0.f;
    for (int j = g; j < deg; j += 4) {
        int s = g_csr_src[base + j];
        float e = lrelu(g_as1[s * HEADS + h] + adh);
        sum += __expf(e - m);
    }
    sum += __shfl_xor_sync(0xffffffffu, sum, 8);
    sum += __shfl_xor_sync(0xffffffffu, sum, 16);
    float inv = 1.0f / (sum + 1e-16f);

    // phase C layout: lane covers 8 channels [lane*8, lane*8+8) -> head = lane>>2
    int hc = lane >> 2;
    float m_c   = __shfl_sync(0xffffffffu, m,   hc);
    float inv_c = __shfl_sync(0xffffffffu, inv, hc);
    float ad_c  = g_ad1[n * HEADS + hc];

    float4 acc0 = make_float4(0.f, 0.f, 0.f, 0.f);
    float4 acc1 = make_float4(0.f, 0.f, 0.f, 0.f);
    const float4* h1v = reinterpret_cast<const float4*>(g_h1);
    for (int j = 0; j < deg; j++) {
        int s = g_csr_src[base + j];                 // broadcast load
        float e = lrelu(g_as1[s * HEADS + hc] + ad_c);
        float alpha = __expf(e - m_c) * inv_c;
        float4 v0 = h1v[s * 64 + lane * 2];
        float4 v1 = h1v[s * 64 + lane * 2 + 1];
        acc0.x = fmaf(alpha, v0.x, acc0.x);
        acc0.y = fmaf(alpha, v0.y, acc0.y);
        acc0.z = fmaf(alpha, v0.z, acc0.z);
        acc0.w = fmaf(alpha, v0.w, acc0.w);
        acc1.x = fmaf(alpha, v1.x, acc1.x);
        acc1.y = fmaf(alpha, v1.y, acc1.y);
        acc1.z = fmaf(alpha, v1.z, acc1.z);
        acc1.w = fmaf(alpha, v1.w, acc1.w);
    }
    // + bias1 (zeros, but keep general), then ELU
    int c0 = lane * 8;
    float b[8];
    #pragma unroll
    for (int i = 0; i < 8; i++) b[i] = bias1[c0 + i];
    float o[8] = {acc0.x + b[0], acc0.y + b[1], acc0.z + b[2], acc0.w + b[3],
                  acc1.x + b[4], acc1.y + b[5], acc1.z + b[6], acc1.w + b[7]};
    #pragma unroll
    for (int i = 0; i < 8; i++) o[i] = o[i] > 0.f ? o[i] : expm1f(o[i]);
    float4* outv = reinterpret_cast<float4*>(g_hmid);
    outv[n * 64 + lane * 2]     = make_float4(o[0], o[1], o[2], o[3]);
    outv[n * 64 + lane * 2 + 1] = make_float4(o[4], o[5], o[6], o[7]);
}

// ---------------- layer 2: node transform (256 -> 16) -----------------------
// block = 256 threads = 16 nodes x 16 channel-threads; W2 staged in smem
__global__ void k_l2_node(const float* __restrict__ W2,
                          const float* __restrict__ att_s,
                          const float* __restrict__ att_d) {
    __shared__ float W2s[D1 * D2];   // 16 KB
    for (int i = threadIdx.x; i < D1 * D2; i += 256) W2s[i] = W2[i];
    __syncthreads();

    int grp = threadIdx.x >> 4;
    int c   = threadIdx.x & 15;
    int n = blockIdx.x * 16 + grp;
    if (n >= NN) return;

    const float4* row = reinterpret_cast<const float4*>(g_hmid + n * D1);
    float acc = 0.f;
    #pragma unroll 4
    for (int k4 = 0; k4 < 64; k4++) {
        float4 v = row[k4];
        int k = k4 * 4;
        acc = fmaf(v.x, W2s[(k + 0) * D2 + c], acc);
        acc = fmaf(v.y, W2s[(k + 1) * D2 + c], acc);
        acc = fmaf(v.z, W2s[(k + 2) * D2 + c], acc);
        acc = fmaf(v.w, W2s[(k + 3) * D2 + c], acc);
    }
    g_h2[n * D2 + c] = acc;
    float sa = acc * att_s[c];
    float sd = acc * att_d[c];
    #pragma unroll
    for (int off = 8; off > 0; off >>= 1) {
        sa += __shfl_xor_sync(0xffffffffu, sa, off);
        sd += __shfl_xor_sync(0xffffffffu, sd, off);
    }
    if (c == 0) { g_as2[n] = sa; g_ad2[n] = sd; }
}

// ---------------- layer 2: softmax + aggregate + bias -----------------------
// one warp per dst node; single head, 16 channels
__global__ void k_l2_agg(const float* __restrict__ bias2,
                         float* __restrict__ out) {
    int n = blockIdx.x * 8 + (threadIdx.x >> 5);
    if (n >= NN) return;
    int lane = threadIdx.x & 31;
    int base = g_offsets[n];
    int deg  = g_offsets[n + 1] - base;
    float adn = g_ad2[n];

    float m = __int_as_float(0xff800000);
    for (int j = lane; j < deg; j += 32) {
        int s = g_csr_src[base + j];
        m = fmaxf(m, lrelu(g_as2[s] + adn));
    }
    #pragma unroll
    for (int off = 16; off > 0; off >>= 1)
        m = fmaxf(m, __shfl_xor_sync(0xffffffffu, m, off));

    float sum = 0.f;
    for (int j = lane; j < deg; j += 32) {
        int s = g_csr_src[base + j];
        sum += __expf(lrelu(g_as2[s] + adn) - m);
    }
    #pragma unroll
    for (int off = 16; off > 0; off >>= 1)
        sum += __shfl_xor_sync(0xffffffffu, sum, off);
    float inv = 1.0f / (sum + 1e-16f);

    int c = lane & 15;
    int half = lane >> 4;
    float acc = 0.f;
    for (int j = half; j < deg; j += 2) {
        int s = g_csr_src[base + j];
        float alpha = __expf(lrelu(g_as2[s] + adn) - m) * inv;
        acc = fmaf(alpha, g_h2[s * D2 + c], acc);
    }
    acc += __shfl_down_sync(0xffffffffu, acc, 16);
    if (lane < 16) out[n * D2 + c] = acc + bias2[c];
}

// ---------------- launch -----------------------------------------------------
extern "C" void kernel_launch(void* const* d_in, const int* in_sizes, int n_in,
                              void* d_out, int out_size) {
    const float* x      = (const float*)d_in[0];
    const int*   ei     = (const int*)d_in[1];   // JAX x64 disabled -> int32
    const float* W1     = (const float*)d_in[2];
    const float* atts1  = (const float*)d_in[3];
    const float* attd1  = (const float*)d_in[4];
    const float* bias1  = (const float*)d_in[5];
    const float* W2     = (const float*)d_in[6];
    const float* atts2  = (const float*)d_in[7];
    const float* attd2  = (const float*)d_in[8];
    const float* bias2  = (const float*)d_in[9];
    float* out = (float*)d_out;

    k_zero_deg<<<(NN + 255) / 256, 256>>>();
    k_hist<<<(ETOT + 255) / 256, 256>>>(ei);
    k_scan<<<1, 1024>>>();
    k_scatter<<<(ETOT + 255) / 256, 256>>>(ei);

    k_l1_node<<<2048, 256>>>(x, W1, atts1, attd1);
    k_l1_agg<<<(NN + 7) / 8, 256>>>(bias1);
    k_l2_node<<<(NN + 15) / 16, 256>>>(W2, atts2, attd2);
    k_l2_agg<<<(NN + 7) / 8, 256>>>(bias2, out);
}

// round 3
// speedup vs baseline: 1.1598x; 1.1598x over previous
#include <cuda_runtime.h>
#include <cuda_fp16.h>
#include <math.h>

#define NN 50000
#define NE 800000
#define ETOT (NE + NN)          // edges + self loops
#define HEADS 8
#define HID 32
#define D1 (HEADS * HID)        // 256
#define D2 16
#define NEG_SLOPE 0.2f

// ---------------- scratch (device globals) -----------------------------------
__device__ int g_degree[NN];
__device__ int g_offsets[NN + 1];
__device__ int g_cursor[NN];
__device__ int g_csr_src[ETOT];

__device__ __align__(16) __half g_h1h[NN * D1];   // layer1 features, fp16
__device__ float g_as1[NN * HEADS];
__device__ float g_ad1[NN * HEADS];
__device__ __align__(16) float g_hmid[NN * D1];   // elu(layer1 out)
__device__ __align__(16) float g_h2[NN * D2];
__device__ float g_as2[NN];
__device__ float g_ad2[NN];
__device__ float g_As1[24];   // [i][h]: att-src matrix folded through W1 (3x8)
__device__ float g_Ad1[24];

__device__ __forceinline__ float lrelu(float x) {
    return x > 0.f ? x : NEG_SLOPE * x;
}

// ---------------- CSR build ---------------------------------------------------
__global__ void k_zero_deg() {
    int i = blockIdx.x * blockDim.x + threadIdx.x;
    if (i < NN) g_degree[i] = 0;
}

__global__ void k_hist(const int* __restrict__ ei) {
    int e = blockIdx.x * blockDim.x + threadIdx.x;
    if (e >= ETOT) return;
    int dst = (e < NE) ? ei[NE + e] : (e - NE);
    atomicAdd(&g_degree[dst], 1);
}

__global__ void k_scan() {
    __shared__ int sh[1024];
    int t = threadIdx.x;
    const int CH = (NN + 1023) >> 10;   // 49
    int b = t * CH;
    int e = min(b + CH, NN);
    int s = 0;
    for (int i = b; i < e; i++) s += g_degree[i];
    sh[t] = s;
    __syncthreads();
    for (int off = 1; off < 1024; off <<= 1) {
        int v = 0;
        if (t >= off) v = sh[t - off];
        __syncthreads();
        sh[t] += v;
        __syncthreads();
    }
    int run = (t == 0) ? 0 : sh[t - 1];
    for (int i = b; i < e; i++) {
        g_offsets[i] = run;
        g_cursor[i]  = run;
        run += g_degree[i];
    }
    if (t == 1023) g_offsets[NN] = sh[1023];
}

__global__ void k_scatter(const int* __restrict__ ei) {
    int e = blockIdx.x * blockDim.x + threadIdx.x;
    if (e >= ETOT) return;
    int src, dst;
    if (e < NE) { src = ei[e]; dst = ei[NE + e]; }
    else        { src = e - NE; dst = e - NE; }
    int slot = atomicAdd(&g_cursor[dst], 1);
    g_csr_src[slot] = src;
}

// ---------------- precompute folded attention matrices (3x8) -----------------
__global__ void k_prep(const float* __restrict__ W1,
                       const float* __restrict__ att_s,
                       const float* __restrict__ att_d) {
    int t = threadIdx.x;
    if (t >= 24) return;
    int i = t >> 3;       // input channel 0..2
    int h = t & 7;        // head
    float ss = 0.f, sd = 0.f;
    #pragma unroll
    for (int c = 0; c < HID; c++) {
        float w = W1[i * D1 + h * HID + c];
        ss = fmaf(w, att_s[h * HID + c], ss);
        sd = fmaf(w, att_d[h * HID + c], sd);
    }
    g_As1[t] = ss;
    g_Ad1[t] = sd;
}

// ---------------- layer 1: node transform (3 -> 256, fp16 out) ---------------
__global__ void k_l1_node(const float* __restrict__ x,
                          const float* __restrict__ W1) {
    int k = threadIdx.x;   // output channel
    float w0 = W1[k], w1 = W1[256 + k], w2 = W1[512 + k];
    for (int n = blockIdx.x; n < NN; n += gridDim.x) {
        float x0 = __ldg(&x[n * 3 + 0]);
        float x1 = __ldg(&x[n * 3 + 1]);
        float x2 = __ldg(&x[n * 3 + 2]);
        float h = fmaf(x0, w0, fmaf(x1, w1, x2 * w2));
        g_h1h[n * D1 + k] = __float2half_rn(h);
        if (k < 8) {
            g_as1[n * 8 + k] = fmaf(x0, g_As1[k], fmaf(x1, g_As1[8 + k], x2 * g_As1[16 + k]));
        } else if (k < 16) {
            int hh = k - 8;
            g_ad1[n * 8 + hh] = fmaf(x0, g_Ad1[hh], fmaf(x1, g_Ad1[8 + hh], x2 * g_Ad1[16 + hh]));
        }
    }
}

// ---------------- layer 1: single-pass softmax-agg + bias + ELU --------------
// one warp per dst node; lane covers channels [lane*8, lane*8+8), head = lane>>2
__global__ void k_l1_agg(const float* __restrict__ bias1) {
    int n = blockIdx.x * 8 + (threadIdx.x >> 5);
    if (n >= NN) return;
    int lane = threadIdx.x & 31;
    int base = g_offsets[n];
    int deg  = g_offsets[n + 1] - base;

    int hc = lane >> 2;
    float ad_c = g_ad1[n * 8 + hc];

    float wsum = 0.f;
    float a0 = 0.f, a1 = 0.f, a2 = 0.f, a3 = 0.f, a4 = 0.f, a5 = 0.f, a6 = 0.f, a7 = 0.f;
    const uint4* h1v = reinterpret_cast<const uint4*>(g_h1h);

    for (int j0 = 0; j0 < deg; j0 += 32) {
        int cnt = min(32, deg - j0);
        int myidx = (lane < cnt) ? g_csr_src[base + j0 + lane] : 0;
        for (int jj = 0; jj < cnt; jj++) {
            int s = __shfl_sync(0xffffffffu, myidx, jj);
            float e = lrelu(g_as1[s * 8 + hc] + ad_c);
            float w = __expf(e);
            wsum += w;
            uint4 v = h1v[s * 32 + lane];
            __half2 p0 = *reinterpret_cast<__half2*>(&v.x);
            __half2 p1 = *reinterpret_cast<__half2*>(&v.y);
            __half2 p2 = *reinterpret_cast<__half2*>(&v.z);
            __half2 p3 = *reinterpret_cast<__half2*>(&v.w);
            float2 f0 = __half22float2(p0);
            float2 f1 = __half22float2(p1);
            float2 f2 = __half22float2(p2);
            float2 f3 = __half22float2(p3);
            a0 = fmaf(w, f0.x, a0); a1 = fmaf(w, f0.y, a1);
            a2 = fmaf(w, f1.x, a2); a3 = fmaf(w, f1.y, a3);
            a4 = fmaf(w, f2.x, a4); a5 = fmaf(w, f2.y, a5);
            a6 = fmaf(w, f3.x, a6); a7 = fmaf(w, f3.y, a7);
        }
    }
    float inv = 1.0f / (wsum + 1e-16f);
    int c0 = lane * 8;
    float o[8] = {a0 * inv + bias1[c0 + 0], a1 * inv + bias1[c0 + 1],
                  a2 * inv + bias1[c0 + 2], a3 * inv + bias1[c0 + 3],
                  a4 * inv + bias1[c0 + 4], a5 * inv + bias1[c0 + 5],
                  a6 * inv + bias1[c0 + 6], a7 * inv + bias1[c0 + 7]};
    #pragma unroll
    for (int i = 0; i < 8; i++) o[i] = o[i] > 0.f ? o[i] : expm1f(o[i]);
    float4* outv = reinterpret_cast<float4*>(g_hmid);
    outv[n * 64 + lane * 2]     = make_float4(o[0], o[1], o[2], o[3]);
    outv[n * 64 + lane * 2 + 1] = make_float4(o[4], o[5], o[6], o[7]);
}

// ---------------- layer 2: node transform (256 -> 16) ------------------------
__global__ void k_l2_node(const float* __restrict__ W2,
                          const float* __restrict__ att_s,
                          const float* __restrict__ att_d) {
    __shared__ float W2s[D1 * D2];   // 16 KB
    for (int i = threadIdx.x; i < D1 * D2; i += 256) W2s[i] = W2[i];
    __syncthreads();

    int grp = threadIdx.x >> 4;
    int c   = threadIdx.x & 15;
    int n = blockIdx.x * 16 + grp;
    if (n >= NN) return;

    const float4* row = reinterpret_cast<const float4*>(g_hmid + n * D1);
    float acc = 0.f;
    #pragma unroll 4
    for (int k4 = 0; k4 < 64; k4++) {
        float4 v = row[k4];
        int k = k4 * 4;
        acc = fmaf(v.x, W2s[(k + 0) * D2 + c], acc);
        acc = fmaf(v.y, W2s[(k + 1) * D2 + c], acc);
        acc = fmaf(v.z, W2s[(k + 2) * D2 + c], acc);
        acc = fmaf(v.w, W2s[(k + 3) * D2 + c], acc);
    }
    g_h2[n * D2 + c] = acc;
    float sa = acc * att_s[c];
    float sd = acc * att_d[c];
    #pragma unroll
    for (int off = 8; off > 0; off >>= 1) {
        sa += __shfl_xor_sync(0xffffffffu, sa, off);
        sd += __shfl_xor_sync(0xffffffffu, sd, off);
    }
    if (c == 0) { g_as2[n] = sa; g_ad2[n] = sd; }
}

// ---------------- layer 2: single-pass softmax-agg + bias --------------------
// one warp per dst node; 2 edges in flight (lane halves), 16 channels each
__global__ void k_l2_agg(const float* __restrict__ bias2,
                         float* __restrict__ out) {
    int n = blockIdx.x * 8 + (threadIdx.x >> 5);
    if (n >= NN) return;
    int lane = threadIdx.x & 31;
    int base = g_offsets[n];
    int deg  = g_offsets[n + 1] - base;
    float adn = g_ad2[n];

    int c = lane & 15;
    int half = lane >> 4;
    float acc = 0.f, wsum = 0.f;
    for (int j = half; j < deg; j += 2) {
        int s = g_csr_src[base + j];
        float w = __expf(lrelu(g_as2[s] + adn));
        acc = fmaf(w, g_h2[s * D2 + c], acc);
        wsum += w;
    }
    acc  += __shfl_down_sync(0xffffffffu, acc, 16);
    wsum += __shfl_down_sync(0xffffffffu, wsum, 16);
    if (lane < 16) out[n * D2 + c] = acc / (wsum + 1e-16f) + bias2[c];
}

// ---------------- launch ------------------------------------------------------
extern "C" void kernel_launch(void* const* d_in, const int* in_sizes, int n_in,
                              void* d_out, int out_size) {
    const float* x      = (const float*)d_in[0];
    const int*   ei     = (const int*)d_in[1];   // JAX x64 disabled -> int32
    const float* W1     = (const float*)d_in[2];
    const float* atts1  = (const float*)d_in[3];
    const float* attd1  = (const float*)d_in[4];
    const float* bias1  = (const float*)d_in[5];
    const float* W2     = (const float*)d_in[6];
    const float* atts2  = (const float*)d_in[7];
    const float* attd2  = (const float*)d_in[8];
    const float* bias2  = (const float*)d_in[9];
    float* out = (float*)d_out;

    k_zero_deg<<<(NN + 255) / 256, 256>>>();
    k_hist<<<(ETOT + 255) / 256, 256>>>(ei);
    k_scan<<<1, 1024>>>();
    k_scatter<<<(ETOT + 255) / 256, 256>>>(ei);

    k_prep<<<1, 32>>>(W1, atts1, attd1);
    k_l1_node<<<2048, 256>>>(x, W1);
    k_l1_agg<<<(NN + 7) / 8, 256>>>(bias1);
    k_l2_node<<<(NN + 15) / 16, 256>>>(W2, atts2, attd2);
    k_l2_agg<<<(NN + 7) / 8, 256>>>(bias2, out);
}

// round 4
// speedup vs baseline: 1.5840x; 1.3657x over previous
#include <cuda_runtime.h>
#include <cuda_fp16.h>
#include <math.h>

#define NN 50000
#define NE 800000
#define ETOT (NE + NN)          // edges + self loops
#define HEADS 8
#define HID 32
#define D1 (HEADS * HID)        // 256
#define D2 16
#define NEG_SLOPE 0.2f

// ---------------- scratch (device globals) -----------------------------------
__device__ int g_degree[NN];
__device__ int g_offsets[NN + 1];
__device__ int g_cursor[NN];
__device__ int g_csr_src[ETOT];

__device__ __align__(16) __half g_hmid_h[NN * D1];  // elu(layer1 out), fp16
__device__ __align__(16) __half g_h2h[NN * D2];     // layer2 features, fp16
__device__ float g_as2[NN];
__device__ float g_ad2[NN];
__device__ float g_As1[24];   // [i][h]: att_src folded through W1 (3x8)
__device__ float g_Ad1[24];   // [i][h]: att_dst folded through W1 (3x8)

__device__ __forceinline__ float lrelu(float x) {
    return x > 0.f ? x : NEG_SLOPE * x;
}

// ---------------- CSR build ---------------------------------------------------
__global__ void k_zero_deg() {
    int i = blockIdx.x * blockDim.x + threadIdx.x;
    if (i < NN) g_degree[i] = 0;
}

__global__ void k_hist(const int* __restrict__ ei) {
    int e = blockIdx.x * blockDim.x + threadIdx.x;
    if (e >= ETOT) return;
    int dst = (e < NE) ? ei[NE + e] : (e - NE);
    atomicAdd(&g_degree[dst], 1);
}

__global__ void k_scan() {
    __shared__ int sh[1024];
    int t = threadIdx.x;
    const int CH = (NN + 1023) >> 10;   // 49
    int b = t * CH;
    int e = min(b + CH, NN);
    int s = 0;
    for (int i = b; i < e; i++) s += g_degree[i];
    sh[t] = s;
    __syncthreads();
    for (int off = 1; off < 1024; off <<= 1) {
        int v = 0;
        if (t >= off) v = sh[t - off];
        __syncthreads();
        sh[t] += v;
        __syncthreads();
    }
    int run = (t == 0) ? 0 : sh[t - 1];
    for (int i = b; i < e; i++) {
        g_offsets[i] = run;
        g_cursor[i]  = run;
        run += g_degree[i];
    }
    if (t == 1023) g_offsets[NN] = sh[1023];
}

__global__ void k_scatter(const int* __restrict__ ei) {
    int e = blockIdx.x * blockDim.x + threadIdx.x;
    if (e >= ETOT) return;
    int src, dst;
    if (e < NE) { src = ei[e]; dst = ei[NE + e]; }
    else        { src = e - NE; dst = e - NE; }
    int slot = atomicAdd(&g_cursor[dst], 1);
    g_csr_src[slot] = src;
}

// ---------------- precompute folded attention matrices (3x8) -----------------
__global__ void k_prep(const float* __restrict__ W1,
                       const float* __restrict__ att_s,
                       const float* __restrict__ att_d) {
    int t = threadIdx.x;
    if (t >= 24) return;
    int i = t >> 3;       // input channel 0..2
    int h = t & 7;        // head
    float ss = 0.f, sd = 0.f;
    #pragma unroll
    for (int c = 0; c < HID; c++) {
        float w = W1[i * D1 + h * HID + c];
        ss = fmaf(w, att_s[h * HID + c], ss);
        sd = fmaf(w, att_d[h * HID + c], sd);
    }
    g_As1[i * 8 + h] = ss;
    g_Ad1[i * 8 + h] = sd;
}

// ---------------- layer 1: fused gather-softmax-agg-transform + ELU ----------
// one warp per dst node. Per edge we gather only x[src] (3 floats); the
// per-head aggregate (sx,sy,sz) is pushed through W1 once per node.
__global__ void k_l1_agg(const float* __restrict__ x,
                         const float* __restrict__ W1,
                         const float* __restrict__ bias1) {
    __shared__ float W1s[768];
    __shared__ float b1s[256];
    for (int i = threadIdx.x; i < 768; i += 256) W1s[i] = W1[i];
    b1s[threadIdx.x] = bias1[threadIdx.x];
    __syncthreads();

    int n = blockIdx.x * 8 + (threadIdx.x >> 5);
    if (n >= NN) return;
    int lane = threadIdx.x & 31;
    int base = g_offsets[n];
    int deg  = g_offsets[n + 1] - base;

    int h = lane & 7;     // head
    int g = lane >> 3;    // edge subgroup (4 edges in flight)

    float A0 = g_As1[h], A1 = g_As1[8 + h], A2 = g_As1[16 + h];
    float xn0 = __ldg(&x[n * 3 + 0]);
    float xn1 = __ldg(&x[n * 3 + 1]);
    float xn2 = __ldg(&x[n * 3 + 2]);
    float adh = fmaf(xn0, g_Ad1[h], fmaf(xn1, g_Ad1[8 + h], xn2 * g_Ad1[16 + h]));

    float sx = 0.f, sy = 0.f, sz = 0.f, sw = 0.f;
    const unsigned FULL = 0xffffffffu;

    for (int j0 = 0; j0 < deg; j0 += 32) {
        int cnt = min(32, deg - j0);
        int myidx = (lane < cnt) ? g_csr_src[base + j0 + lane] : 0;
        for (int jj = 0; jj < cnt; jj += 4) {
            int e = jj + g;
            bool valid = e < cnt;
            int s = __shfl_sync(FULL, myidx, valid ? e : (cnt - 1));
            float xv = (h < 3) ? __ldg(&x[s * 3 + h]) : 0.f;
            float x0 = __shfl_sync(FULL, xv, g * 8 + 0);
            float x1 = __shfl_sync(FULL, xv, g * 8 + 1);
            float x2 = __shfl_sync(FULL, xv, g * 8 + 2);
            float w = 0.f;
            if (valid) {
                float as = fmaf(x0, A0, fmaf(x1, A1, x2 * A2));
                w = __expf(lrelu(as + adh));
            }
            sw += w;
            sx = fmaf(w, x0, sx);
            sy = fmaf(w, x1, sy);
            sz = fmaf(w, x2, sz);
        }
    }
    #pragma unroll
    for (int off = 8; off <= 16; off <<= 1) {
        sx += __shfl_xor_sync(FULL, sx, off);
        sy += __shfl_xor_sync(FULL, sy, off);
        sz += __shfl_xor_sync(FULL, sz, off);
        sw += __shfl_xor_sync(FULL, sw, off);
    }

    int hc = lane >> 2;
    float ex = __shfl_sync(FULL, sx, hc);
    float ey = __shfl_sync(FULL, sy, hc);
    float ez = __shfl_sync(FULL, sz, hc);
    float ew = __shfl_sync(FULL, sw, hc);
    float inv = 1.0f / (ew + 1e-16f);
    ex *= inv; ey *= inv; ez *= inv;

    int c0 = lane * 8;
    float o[8];
    #pragma unroll
    for (int i = 0; i < 8; i++) {
        int k = c0 + i;
        float v = fmaf(ex, W1s[k], fmaf(ey, W1s[256 + k], ez * W1s[512 + k]));
        v += b1s[k];
        o[i] = v > 0.f ? v : expm1f(v);
    }
    __half2 p0 = __floats2half2_rn(o[0], o[1]);
    __half2 p1 = __floats2half2_rn(o[2], o[3]);
    __half2 p2 = __floats2half2_rn(o[4], o[5]);
    __half2 p3 = __floats2half2_rn(o[6], o[7]);
    uint4 pack;
    pack.x = *reinterpret_cast<unsigned int*>(&p0);
    pack.y = *reinterpret_cast<unsigned int*>(&p1);
    pack.z = *reinterpret_cast<unsigned int*>(&p2);
    pack.w = *reinterpret_cast<unsigned int*>(&p3);
    reinterpret_cast<uint4*>(g_hmid_h)[n * 32 + lane] = pack;
}

// ---------------- layer 2: node transform (256 -> 16), fp16 in/out -----------
__global__ void k_l2_node(const float* __restrict__ W2,
                          const float* __restrict__ att_s,
                          const float* __restrict__ att_d) {
    __shared__ float W2s[D1 * D2];   // 16 KB
    for (int i = threadIdx.x; i < D1 * D2; i += 256) W2s[i] = W2[i];
    __syncthreads();

    int grp = threadIdx.x >> 4;
    int c   = threadIdx.x & 15;
    int n = blockIdx.x * 16 + grp;
    if (n >= NN) return;

    const uint4* row = reinterpret_cast<const uint4*>(g_hmid_h + n * D1);
    float acc = 0.f;
    #pragma unroll 8
    for (int q = 0; q < 32; q++) {
        uint4 v = row[q];
        int k = q * 8;
        const __half2* p = reinterpret_cast<const __half2*>(&v);
        #pragma unroll
        for (int t = 0; t < 4; t++) {
            float2 f = __half22float2(p[t]);
            acc = fmaf(f.x, W2s[(k + 2 * t) * D2 + c], acc);
            acc = fmaf(f.y, W2s[(k + 2 * t + 1) * D2 + c], acc);
        }
    }
    g_h2h[n * D2 + c] = __float2half_rn(acc);
    float sa = acc * att_s[c];
    float sd = acc * att_d[c];
    #pragma unroll
    for (int off = 8; off > 0; off >>= 1) {
        sa += __shfl_xor_sync(0xffffffffu, sa, off);
        sd += __shfl_xor_sync(0xffffffffu, sd, off);
    }
    if (c == 0) { g_as2[n] = sa; g_ad2[n] = sd; }
}

// ---------------- layer 2: single-pass softmax-agg + bias --------------------
__global__ void k_l2_agg(const float* __restrict__ bias2,
                         float* __restrict__ out) {
    int n = blockIdx.x * 8 + (threadIdx.x >> 5);
    if (n >= NN) return;
    int lane = threadIdx.x & 31;
    int base = g_offsets[n];
    int deg  = g_offsets[n + 1] - base;
    float adn = g_ad2[n];

    int c = lane & 15;
    int half = lane >> 4;
    float acc = 0.f, wsum = 0.f;
    for (int j = half; j < deg; j += 2) {
        int s = g_csr_src[base + j];
        float w = __expf(lrelu(g_as2[s] + adn));
        acc = fmaf(w, __half2float(g_h2h[s * D2 + c]), acc);
        wsum += w;
    }
    acc  += __shfl_down_sync(0xffffffffu, acc, 16);
    wsum += __shfl_down_sync(0xffffffffu, wsum, 16);
    if (lane < 16) out[n * D2 + c] = acc / (wsum + 1e-16f) + bias2[c];
}

// ---------------- launch ------------------------------------------------------
extern "C" void kernel_launch(void* const* d_in, const int* in_sizes, int n_in,
                              void* d_out, int out_size) {
    const float* x      = (const float*)d_in[0];
    const int*   ei     = (const int*)d_in[1];   // JAX x64 disabled -> int32
    const float* W1     = (const float*)d_in[2];
    const float* atts1  = (const float*)d_in[3];
    const float* attd1  = (const float*)d_in[4];
    const float* bias1  = (const float*)d_in[5];
    const float* W2     = (const float*)d_in[6];
    const float* atts2  = (const float*)d_in[7];
    const float* attd2  = (const float*)d_in[8];
    const float* bias2  = (const float*)d_in[9];
    float* out = (float*)d_out;

    k_zero_deg<<<(NN + 255) / 256, 256>>>();
    k_hist<<<(ETOT + 255) / 256, 256>>>(ei);
    k_scan<<<1, 1024>>>();
    k_scatter<<<(ETOT + 255) / 256, 256>>>(ei);

    k_prep<<<1, 32>>>(W1, atts1, attd1);
    k_l1_agg<<<(NN + 7) / 8, 256>>>(x, W1, bias1);
    k_l2_node<<<(NN + 15) / 16, 256>>>(W2, atts2, attd2);
    k_l2_agg<<<(NN + 7) / 8, 256>>>(bias2, out);
}